// round 9
// baseline (speedup 1.0000x reference)
#include <cuda_runtime.h>

#define CH     512
#define HW     4096        // 64*64
#define NPIX   32768       // 8 * 4096

// Static device scratch (no dynamic allocation allowed).
__device__ float g_recon[NPIX];
__device__ float g_ref[NPIX];

// ---- packed f32x2 helpers (Blackwell FFMA2 path, PTX-only) -----------------
typedef unsigned long long ull;
__device__ __forceinline__ ull pk2(float lo, float hi) {
    ull r; asm("mov.b64 %0, {%1, %2};" : "=l"(r) : "f"(lo), "f"(hi)); return r;
}
__device__ __forceinline__ void unpk2(ull v, float& lo, float& hi) {
    asm("mov.b64 {%0, %1}, %2;" : "=f"(lo), "=f"(hi) : "l"(v));
}
__device__ __forceinline__ ull fma2(ull a, ull b, ull c) {
    ull d; asm("fma.rn.f32x2 %0, %1, %2, %3;" : "=l"(d) : "l"(a), "l"(b), "l"(c));
    return d;
}
__device__ __forceinline__ ull mul2(ull a, ull b) {
    ull d; asm("mul.rn.f32x2 %0, %1, %2;" : "=l"(d) : "l"(a), "l"(b)); return d;
}

// ---------------------------------------------------------------------------
// Kernel A (fused dot + reduce), chunked: chunk c covers 128 of the 512
// 64-px tiles (= batches 2c, 2c+1). Internals identical to R6.
// ---------------------------------------------------------------------------
__global__ void __launch_bounds__(256) k_fused(
        const float* __restrict__ spade, const float* __restrict__ x,
        const float* __restrict__ w1, const float* __restrict__ w2,
        const float* __restrict__ b1, const float* __restrict__ b2,
        int chunk) {
    __shared__ float2 ws[CH];                 // (w1, w2) pairs
    __shared__ float4 red1[16][16];           // [group][float4 slot]
    __shared__ float4 red2[16][16];
    const int t = threadIdx.x;
    for (int c = t; c < CH; c += 256) ws[c] = make_float2(w1[c], w2[c]);
    __syncthreads();

    const int pt  = chunk * 128 + blockIdx.x; // 64-px tile index (0..511)
    const int b   = pt >> 6;                  // batch
    const int hw0 = (pt & 63) * 64;           // tile base within the image
    const int i   = t & 15;                   // float4 slot (4 px)
    const int j   = t >> 4;                   // channel group (32 ch)

    const size_t base = (size_t)b * CH * HW + (size_t)(j * 32) * HW + hw0 + i * 4;
    const float4* fp = (const float4*)(spade + base);
    const float4* xp = (const float4*)(x + base);
    const float2* wp = ws + j * 32;

    float4 a1 = make_float4(0.f, 0.f, 0.f, 0.f);
    float4 a2 = make_float4(0.f, 0.f, 0.f, 0.f);
    #pragma unroll 8
    for (int c = 0; c < 32; c++) {
        float4 f = __ldcs(fp + (size_t)c * (HW / 4));
        float4 v = __ldcs(xp + (size_t)c * (HW / 4));
        const float2 w = wp[c];
        a1.x += f.x * w.x; a1.y += f.y * w.x; a1.z += f.z * w.x; a1.w += f.w * w.x;
        a2.x += v.x * w.y; a2.y += v.y * w.y; a2.z += v.z * w.y; a2.w += v.w * w.y;
    }
    red1[j][i] = a1;
    red2[j][i] = a2;
    __syncthreads();

    if (t < 16) {
        float4 s = make_float4(0.f, 0.f, 0.f, 0.f);
        #pragma unroll
        for (int g = 0; g < 16; g++) {
            const float4 a = red1[g][t];
            s.x += a.x; s.y += a.y; s.z += a.z; s.w += a.w;
        }
        const float bb = b1[0];
        s.x = fmaxf(s.x + bb, 0.f); s.y = fmaxf(s.y + bb, 0.f);
        s.z = fmaxf(s.z + bb, 0.f); s.w = fmaxf(s.w + bb, 0.f);
        *(float4*)&g_recon[pt * 64 + t * 4] = s;
    } else if (t >= 32 && t < 48) {
        const int i2 = t - 32;
        float4 s = make_float4(0.f, 0.f, 0.f, 0.f);
        #pragma unroll
        for (int g = 0; g < 16; g++) {
            const float4 a = red2[g][i2];
            s.x += a.x; s.y += a.y; s.z += a.z; s.w += a.w;
        }
        const float bb = b2[0];
        s.x = fmaxf(s.x + bb, 0.f); s.y = fmaxf(s.y + bb, 0.f);
        s.z = fmaxf(s.z + bb, 0.f); s.w = fmaxf(s.w + bb, 0.f);
        *(float4*)&g_ref[pt * 64 + i2 * 4] = s;
    }
}

// ---------------------------------------------------------------------------
// Kernel B (k_match, R8 internals), chunked: chunk c covers batches 2c, 2c+1
// with 128 blocks of 16 patches each. 8 warps = 4 patch quads x 2 row halves.
// ---------------------------------------------------------------------------
__global__ void __launch_bounds__(256) k_match(float* __restrict__ out, int chunk) {
    __shared__ float Ra[65][68];   // recon tile; row 64 / cols>=64 are zero
    __shared__ float sv[16][2];    // [local patch][row half] best value
    __shared__ int   si[16][2];    // [local patch][row half] best row-base idx
    const int t    = threadIdx.x;
    const int b    = chunk * 2 + (blockIdx.x >> 6);
    const int grp  = blockIdx.x & 63;       // 64 groups of 16 patches
    const float* rb = g_recon + b * HW;

    for (int i = t; i < 65 * 68; i += 256) {
        const int row = i / 68;
        const int col = i - row * 68;
        Ra[row][col] = (row < 64 && col < 64) ? rb[row * 64 + col] : 0.f;
    }
    __syncthreads();

    const int lane = t & 31;
    const int w    = t >> 5;
    const int rh   = w & 1;                 // row half: rows [rh*32, rh*32+32)
    const int pq   = w >> 1;                // patch quad 0..3
    const float* refb = g_ref + b * HW;

    const int l0 = grp * 16 + pq * 4;       // first of 4 patches for this warp

    ull cc[4][4];
    #pragma unroll
    for (int pp = 0; pp < 4; pp++) {
        const int l  = l0 + pp;
        const int pi = l >> 5, pj = l & 31;
        const float c00 = refb[(2 * pi) * 64 + 2 * pj];
        const float c01 = refb[(2 * pi) * 64 + 2 * pj + 1];
        const float c10 = refb[(2 * pi + 1) * 64 + 2 * pj];
        const float c11 = refb[(2 * pi + 1) * 64 + 2 * pj + 1];
        cc[pp][0] = pk2(c00, c00);
        cc[pp][1] = pk2(c01, c01);
        cc[pp][2] = pk2(c10, c10);
        cc[pp][3] = pk2(c11, c11);
    }

    const int q  = lane * 2;
    const int p0 = rh * 32;

    ull cur01 = *(const ull*)&Ra[p0][q];
    float r0h, r1h; unpk2(cur01, r0h, r1h);
    ull v12 = pk2(r1h, Ra[p0][q + 2]);

    float bv[4] = {-1.f, -1.f, -1.f, -1.f};
    int   bi[4] = {0, 0, 0, 0};
    int   idx   = (p0 << 6) + q;            // row-base flat idx for this lane

    #pragma unroll 4
    for (int p = p0; p < p0 + 32; p++) {
        const ull nxt01 = *(const ull*)&Ra[p + 1][q];
        const ull nxt23 = *(const ull*)&Ra[p + 1][q + 2];
        float n0, n1; unpk2(nxt01, n0, n1);
        float n2, nx; unpk2(nxt23, n2, nx);
        const ull w12 = pk2(n1, n2);

        #pragma unroll
        for (int pp = 0; pp < 4; pp++) {
            const ull y = fma2(cc[pp][3], w12, fma2(cc[pp][2], nxt01,
                          fma2(cc[pp][1], v12, mul2(cc[pp][0], cur01))));
            float y0, y1; unpk2(y, y0, y1);
            const float rv = fmaxf(y0, y1);
            if (rv > bv[pp]) { bi[pp] = idx; }
            bv[pp] = fmaxf(bv[pp], rv);
        }
        cur01 = nxt01;
        v12   = w12;
        idx  += 64;
    }

    // Warp argmax per patch; ties -> smallest flat idx (row-major order).
    #pragma unroll
    for (int pp = 0; pp < 4; pp++) {
        float v = bv[pp]; int i0 = bi[pp];
        #pragma unroll
        for (int off = 16; off; off >>= 1) {
            const float v2 = __shfl_down_sync(0xffffffffu, v, off);
            const int   i2 = __shfl_down_sync(0xffffffffu, i0, off);
            if (v2 > v || (v2 == v && i2 < i0)) { v = v2; i0 = i2; }
        }
        if (lane == 0) { sv[pq * 4 + pp][rh] = v; si[pq * 4 + pp][rh] = i0; }
    }
    __syncthreads();

    // Combine halves, decode the column bit (bit-exact recompute), gather.
    if (t < 16) {
        float v = sv[t][0];
        int   bi2 = si[t][0];
        const float v1 = sv[t][1];
        const int   i1 = si[t][1];
        if (v1 > v) { v = v1; bi2 = i1; }    // half-1 rows all larger -> ties keep half 0

        const int l  = grp * 16 + t;
        const int pi = l >> 5, pj = l & 31;
        const float c00 = refb[(2 * pi) * 64 + 2 * pj];
        const float c01 = refb[(2 * pi) * 64 + 2 * pj + 1];
        const float c10 = refb[(2 * pi + 1) * 64 + 2 * pj];
        const float c11 = refb[(2 * pi + 1) * 64 + 2 * pj + 1];

        const int pr = bi2 >> 6;             // winning row
        const int qb = bi2 & 63;             // winning column pair base
        // recompute y0 with identical fma ordering as the packed lo lane
        const float r0 = Ra[pr][qb],     r1 = Ra[pr][qb + 1];
        const float n0 = Ra[pr + 1][qb], n1 = Ra[pr + 1][qb + 1];
        float y0 = c00 * r0;
        y0 = fmaf(c01, r1, y0);
        y0 = fmaf(c10, n0, y0);
        y0 = fmaf(c11, n1, y0);
        const int besti = bi2 + ((y0 == v) ? 0 : 1);  // earlier col on tie

        const int g  = besti >> 2;           // offset // 4
        const int gi = g >> 5, gj = g & 31;
        float* o = out + b * HW + (2 * pi) * 64 + 2 * pj;
        o[0]  = Ra[2 * gi][2 * gj];
        o[1]  = Ra[2 * gi][2 * gj + 1];
        o[64] = Ra[2 * gi + 1][2 * gj];
        o[65] = Ra[2 * gi + 1][2 * gj + 1];
    }
}

// ---------------------------------------------------------------------------
// Launch: 4 chunked k_fused on the main stream; each chunk's k_match runs on
// a side stream gated by an event (fork-join capture pattern). k_match's
// issue-bound warps fill k_fused's memory-stall shadows.
// Streams/events are created lazily ONCE (first, non-captured call); no
// device-memory allocation is involved.
// ---------------------------------------------------------------------------
extern "C" void kernel_launch(void* const* d_in, const int* in_sizes, int n_in,
                              void* d_out, int out_size) {
    const float* spade = (const float*)d_in[0];
    const float* x     = (const float*)d_in[1];
    const float* w1    = (const float*)d_in[2];
    const float* b1    = (const float*)d_in[3];
    const float* w2    = (const float*)d_in[4];
    const float* b2    = (const float*)d_in[5];
    float* out = (float*)d_out;

    static cudaStream_t s2 = nullptr;
    static cudaEvent_t evF[4];
    static cudaEvent_t evJ = nullptr;
    if (s2 == nullptr) {
        cudaStreamCreateWithFlags(&s2, cudaStreamNonBlocking);
        for (int c = 0; c < 4; c++)
            cudaEventCreateWithFlags(&evF[c], cudaEventDisableTiming);
        cudaEventCreateWithFlags(&evJ, cudaEventDisableTiming);
    }

    for (int c = 0; c < 4; c++) {
        k_fused<<<128, 256>>>(spade, x, w1, w2, b1, b2, c);
        cudaEventRecord(evF[c], 0);
        cudaStreamWaitEvent(s2, evF[c], 0);
        k_match<<<128, 256, 0, s2>>>(out, c);
    }
    cudaEventRecord(evJ, s2);
    cudaStreamWaitEvent(0, evJ, 0);
}

// round 10
// speedup vs baseline: 1.4964x; 1.4964x over previous
#include <cuda_runtime.h>

#define CH     512
#define HW     4096        // 64*64
#define NPIX   32768       // 8 * 4096

// Static device scratch (no dynamic allocation allowed).
__device__ float g_recon[NPIX];
__device__ float g_ref[NPIX];
__device__ int   g_cnt[8];     // per-batch completed-tile counters (0..64)

// ---- packed f32x2 helpers (Blackwell FFMA2 path, PTX-only) -----------------
typedef unsigned long long ull;
__device__ __forceinline__ ull pk2(float lo, float hi) {
    ull r; asm("mov.b64 %0, {%1, %2};" : "=l"(r) : "f"(lo), "f"(hi)); return r;
}
__device__ __forceinline__ void unpk2(ull v, float& lo, float& hi) {
    asm("mov.b64 {%0, %1}, %2;" : "=f"(lo), "=f"(hi) : "l"(v));
}
__device__ __forceinline__ ull fma2(ull a, ull b, ull c) {
    ull d; asm("fma.rn.f32x2 %0, %1, %2, %3;" : "=l"(d) : "l"(a), "l"(b), "l"(c));
    return d;
}
__device__ __forceinline__ ull mul2(ull a, ull b) {
    ull d; asm("mul.rn.f32x2 %0, %1, %2;" : "=l"(d) : "l"(a), "l"(b)); return d;
}

// ---------------------------------------------------------------------------
// Counter reset (runs first in the graph each replay).
// ---------------------------------------------------------------------------
__global__ void k_zero() {
    if (threadIdx.x < 8) g_cnt[threadIdx.x] = 0;
}

// ---------------------------------------------------------------------------
// Mega kernel: 768 blocks.
//   blocks 0..255   : fused dot+reduce role, 2 tiles each (pt = bid, bid+256),
//                     batch-ordered so batches 0-3 complete ~half-way.
//   blocks 256..767 : match role (R8 internals), spin on per-batch counter.
// Fused blocks are the lowest indices -> all resident in wave 1 -> guaranteed
// progress; match blocks only read flags (no cyclic wait).
// ---------------------------------------------------------------------------
__global__ void __launch_bounds__(256, 5) k_mega(
        const float* __restrict__ spade, const float* __restrict__ x,
        const float* __restrict__ w1, const float* __restrict__ w2,
        const float* __restrict__ b1, const float* __restrict__ b2,
        float* __restrict__ out) {
    __shared__ __align__(16) unsigned char sbuf[18048];
    const int t = threadIdx.x;

    if (blockIdx.x < 256) {
        // ================= FUSED ROLE =================
        float2* ws = (float2*)sbuf;                                   // 4 KB
        float4 (*red1)[16] = (float4 (*)[16])(sbuf + 4096);           // 4 KB
        float4 (*red2)[16] = (float4 (*)[16])(sbuf + 8192);           // 4 KB

        for (int c = t; c < CH; c += 256) ws[c] = make_float2(w1[c], w2[c]);
        __syncthreads();

        const int i = t & 15;                 // float4 slot (4 px)
        const int j = t >> 4;                 // channel group (32 ch)

        #pragma unroll
        for (int pass = 0; pass < 2; pass++) {
            const int pt  = blockIdx.x + pass * 256;   // tile 0..511
            const int b   = pt >> 6;
            const int hw0 = (pt & 63) * 64;

            const size_t base = (size_t)b * CH * HW + (size_t)(j * 32) * HW
                              + hw0 + i * 4;
            const float4* fp = (const float4*)(spade + base);
            const float4* xp = (const float4*)(x + base);
            const float2* wp = ws + j * 32;

            float4 a1 = make_float4(0.f, 0.f, 0.f, 0.f);
            float4 a2 = make_float4(0.f, 0.f, 0.f, 0.f);
            #pragma unroll 8
            for (int c = 0; c < 32; c++) {
                float4 f = __ldcs(fp + (size_t)c * (HW / 4));
                float4 v = __ldcs(xp + (size_t)c * (HW / 4));
                const float2 w = wp[c];
                a1.x += f.x * w.x; a1.y += f.y * w.x;
                a1.z += f.z * w.x; a1.w += f.w * w.x;
                a2.x += v.x * w.y; a2.y += v.y * w.y;
                a2.z += v.z * w.y; a2.w += v.w * w.y;
            }
            __syncthreads();              // prior pass's reduction reads done
            red1[j][i] = a1;
            red2[j][i] = a2;
            __syncthreads();

            if (t < 16) {
                float4 s = make_float4(0.f, 0.f, 0.f, 0.f);
                #pragma unroll
                for (int g = 0; g < 16; g++) {
                    const float4 a = red1[g][t];
                    s.x += a.x; s.y += a.y; s.z += a.z; s.w += a.w;
                }
                const float bb = b1[0];
                s.x = fmaxf(s.x + bb, 0.f); s.y = fmaxf(s.y + bb, 0.f);
                s.z = fmaxf(s.z + bb, 0.f); s.w = fmaxf(s.w + bb, 0.f);
                *(float4*)&g_recon[pt * 64 + t * 4] = s;
                __threadfence();
            } else if (t >= 32 && t < 48) {
                const int i2 = t - 32;
                float4 s = make_float4(0.f, 0.f, 0.f, 0.f);
                #pragma unroll
                for (int g = 0; g < 16; g++) {
                    const float4 a = red2[g][i2];
                    s.x += a.x; s.y += a.y; s.z += a.z; s.w += a.w;
                }
                const float bb = b2[0];
                s.x = fmaxf(s.x + bb, 0.f); s.y = fmaxf(s.y + bb, 0.f);
                s.z = fmaxf(s.z + bb, 0.f); s.w = fmaxf(s.w + bb, 0.f);
                *(float4*)&g_ref[pt * 64 + i2 * 4] = s;
                __threadfence();
            }
            __syncthreads();
            if (t == 0) atomicAdd(&g_cnt[b], 1);
        }
        return;
    }

    // ================= MATCH ROLE =================
    float (*Ra)[68] = (float (*)[68])sbuf;                      // 17680 B
    float* sv = (float*)(sbuf + 17680);                         // [16][2]
    int*   si = (int*)(sbuf + 17808);                           // [16][2]

    const int bid  = blockIdx.x - 256;       // 0..511
    const int b    = bid >> 6;
    const int grp  = bid & 63;               // 64 groups of 16 patches

    // Wait until this batch's 64 tiles are complete.
    if (t == 0) {
        while (atomicAdd(&g_cnt[b], 0) < 64) __nanosleep(128);
        __threadfence();
    }
    __syncthreads();

    const float* rb = g_recon + b * HW;
    for (int i = t; i < 65 * 68; i += 256) {
        const int row = i / 68;
        const int col = i - row * 68;
        Ra[row][col] = (row < 64 && col < 64) ? rb[row * 64 + col] : 0.f;
    }
    __syncthreads();

    const int lane = t & 31;
    const int w    = t >> 5;
    const int rh   = w & 1;                  // row half
    const int pq   = w >> 1;                 // patch quad 0..3
    const float* refb = g_ref + b * HW;

    const int l0 = grp * 16 + pq * 4;

    ull cc[4][4];
    #pragma unroll
    for (int pp = 0; pp < 4; pp++) {
        const int l  = l0 + pp;
        const int pi = l >> 5, pj = l & 31;
        const float c00 = refb[(2 * pi) * 64 + 2 * pj];
        const float c01 = refb[(2 * pi) * 64 + 2 * pj + 1];
        const float c10 = refb[(2 * pi + 1) * 64 + 2 * pj];
        const float c11 = refb[(2 * pi + 1) * 64 + 2 * pj + 1];
        cc[pp][0] = pk2(c00, c00);
        cc[pp][1] = pk2(c01, c01);
        cc[pp][2] = pk2(c10, c10);
        cc[pp][3] = pk2(c11, c11);
    }

    const int q  = lane * 2;
    const int p0 = rh * 32;

    ull cur01 = *(const ull*)&Ra[p0][q];
    float r0h, r1h; unpk2(cur01, r0h, r1h);
    ull v12 = pk2(r1h, Ra[p0][q + 2]);

    float bv[4] = {-1.f, -1.f, -1.f, -1.f};
    int   bi[4] = {0, 0, 0, 0};
    int   idx   = (p0 << 6) + q;

    #pragma unroll 4
    for (int p = p0; p < p0 + 32; p++) {
        const ull nxt01 = *(const ull*)&Ra[p + 1][q];
        const ull nxt23 = *(const ull*)&Ra[p + 1][q + 2];
        float n0, n1; unpk2(nxt01, n0, n1);
        float n2, nx; unpk2(nxt23, n2, nx);
        const ull w12 = pk2(n1, n2);

        #pragma unroll
        for (int pp = 0; pp < 4; pp++) {
            const ull y = fma2(cc[pp][3], w12, fma2(cc[pp][2], nxt01,
                          fma2(cc[pp][1], v12, mul2(cc[pp][0], cur01))));
            float y0, y1; unpk2(y, y0, y1);
            const float rv = fmaxf(y0, y1);
            if (rv > bv[pp]) { bi[pp] = idx; }
            bv[pp] = fmaxf(bv[pp], rv);
        }
        cur01 = nxt01;
        v12   = w12;
        idx  += 64;
    }

    // Warp argmax per patch; ties -> smallest flat idx (row-major order).
    #pragma unroll
    for (int pp = 0; pp < 4; pp++) {
        float v = bv[pp]; int i0 = bi[pp];
        #pragma unroll
        for (int off = 16; off; off >>= 1) {
            const float v2 = __shfl_down_sync(0xffffffffu, v, off);
            const int   i2 = __shfl_down_sync(0xffffffffu, i0, off);
            if (v2 > v || (v2 == v && i2 < i0)) { v = v2; i0 = i2; }
        }
        if (lane == 0) {
            sv[(pq * 4 + pp) * 2 + rh] = v;
            si[(pq * 4 + pp) * 2 + rh] = i0;
        }
    }
    __syncthreads();

    // Combine halves, decode the column bit (bit-exact recompute), gather.
    if (t < 16) {
        float v   = sv[t * 2 + 0];
        int   bi2 = si[t * 2 + 0];
        const float v1 = sv[t * 2 + 1];
        const int   i1 = si[t * 2 + 1];
        if (v1 > v) { v = v1; bi2 = i1; }   // half-1 rows larger -> ties keep half 0

        const int l  = grp * 16 + t;
        const int pi = l >> 5, pj = l & 31;
        const float c00 = refb[(2 * pi) * 64 + 2 * pj];
        const float c01 = refb[(2 * pi) * 64 + 2 * pj + 1];
        const float c10 = refb[(2 * pi + 1) * 64 + 2 * pj];
        const float c11 = refb[(2 * pi + 1) * 64 + 2 * pj + 1];

        const int pr = bi2 >> 6;             // winning row
        const int qb = bi2 & 63;             // winning column pair base
        const float r0 = Ra[pr][qb],     r1 = Ra[pr][qb + 1];
        const float n0 = Ra[pr + 1][qb], n1 = Ra[pr + 1][qb + 1];
        float y0 = c00 * r0;
        y0 = fmaf(c01, r1, y0);
        y0 = fmaf(c10, n0, y0);
        y0 = fmaf(c11, n1, y0);
        const int besti = bi2 + ((y0 == v) ? 0 : 1);  // earlier col on tie

        const int g  = besti >> 2;           // offset // 4
        const int gi = g >> 5, gj = g & 31;
        float* o = out + b * HW + (2 * pi) * 64 + 2 * pj;
        o[0]  = Ra[2 * gi][2 * gj];
        o[1]  = Ra[2 * gi][2 * gj + 1];
        o[64] = Ra[2 * gi + 1][2 * gj];
        o[65] = Ra[2 * gi + 1][2 * gj + 1];
    }
}

extern "C" void kernel_launch(void* const* d_in, const int* in_sizes, int n_in,
                              void* d_out, int out_size) {
    const float* spade = (const float*)d_in[0];
    const float* x     = (const float*)d_in[1];
    const float* w1    = (const float*)d_in[2];
    const float* b1    = (const float*)d_in[3];
    const float* w2    = (const float*)d_in[4];
    const float* b2    = (const float*)d_in[5];
    float* out = (float*)d_out;

    k_zero<<<1, 32>>>();
    k_mega<<<768, 256>>>(spade, x, w1, w2, b1, b2, out);
}

// round 11
// speedup vs baseline: 1.8185x; 1.2153x over previous
#include <cuda_runtime.h>

#define CH     512
#define HW     4096        // 64*64
#define NPIX   32768       // 8 * 4096

// Static device scratch (no dynamic allocation allowed).
__device__ float g_recon[NPIX];
__device__ float g_ref[NPIX];

// ---- packed f32x2 helpers (Blackwell FFMA2 path, PTX-only) -----------------
typedef unsigned long long ull;
__device__ __forceinline__ ull pk2(float lo, float hi) {
    ull r; asm("mov.b64 %0, {%1, %2};" : "=l"(r) : "f"(lo), "f"(hi)); return r;
}
__device__ __forceinline__ void unpk2(ull v, float& lo, float& hi) {
    asm("mov.b64 {%0, %1}, %2;" : "=f"(lo), "=f"(hi) : "l"(v));
}
__device__ __forceinline__ ull fma2(ull a, ull b, ull c) {
    ull d; asm("fma.rn.f32x2 %0, %1, %2, %3;" : "=l"(d) : "l"(a), "l"(b), "l"(c));
    return d;
}
__device__ __forceinline__ ull mul2(ull a, ull b) {
    ull d; asm("mul.rn.f32x2 %0, %1, %2;" : "=l"(d) : "l"(a), "l"(b)); return d;
}

// ---------------------------------------------------------------------------
// Kernel A (fused dot + reduce) — unchanged from R6 (near DRAM roof).
// ---------------------------------------------------------------------------
__global__ void __launch_bounds__(256) k_fused(
        const float* __restrict__ spade, const float* __restrict__ x,
        const float* __restrict__ w1, const float* __restrict__ w2,
        const float* __restrict__ b1, const float* __restrict__ b2) {
    __shared__ float2 ws[CH];                 // (w1, w2) pairs
    __shared__ float4 red1[16][16];           // [group][float4 slot]
    __shared__ float4 red2[16][16];
    const int t = threadIdx.x;
    for (int c = t; c < CH; c += 256) ws[c] = make_float2(w1[c], w2[c]);
    __syncthreads();

    const int pt  = blockIdx.x;               // 64-px tile index (0..511)
    const int b   = pt >> 6;                  // batch
    const int hw0 = (pt & 63) * 64;           // tile base within the image
    const int i   = t & 15;                   // float4 slot (4 px)
    const int j   = t >> 4;                   // channel group (32 ch)

    const size_t base = (size_t)b * CH * HW + (size_t)(j * 32) * HW + hw0 + i * 4;
    const float4* fp = (const float4*)(spade + base);
    const float4* xp = (const float4*)(x + base);
    const float2* wp = ws + j * 32;

    float4 a1 = make_float4(0.f, 0.f, 0.f, 0.f);
    float4 a2 = make_float4(0.f, 0.f, 0.f, 0.f);
    #pragma unroll 8
    for (int c = 0; c < 32; c++) {
        float4 f = __ldcs(fp + (size_t)c * (HW / 4));
        float4 v = __ldcs(xp + (size_t)c * (HW / 4));
        const float2 w = wp[c];
        a1.x += f.x * w.x; a1.y += f.y * w.x; a1.z += f.z * w.x; a1.w += f.w * w.x;
        a2.x += v.x * w.y; a2.y += v.y * w.y; a2.z += v.z * w.y; a2.w += v.w * w.y;
    }
    red1[j][i] = a1;
    red2[j][i] = a2;
    __syncthreads();

    if (t < 16) {
        float4 s = make_float4(0.f, 0.f, 0.f, 0.f);
        #pragma unroll
        for (int g = 0; g < 16; g++) {
            const float4 a = red1[g][t];
            s.x += a.x; s.y += a.y; s.z += a.z; s.w += a.w;
        }
        const float bb = b1[0];
        s.x = fmaxf(s.x + bb, 0.f); s.y = fmaxf(s.y + bb, 0.f);
        s.z = fmaxf(s.z + bb, 0.f); s.w = fmaxf(s.w + bb, 0.f);
        *(float4*)&g_recon[pt * 64 + t * 4] = s;
    } else if (t >= 32 && t < 48) {
        const int i2 = t - 32;
        float4 s = make_float4(0.f, 0.f, 0.f, 0.f);
        #pragma unroll
        for (int g = 0; g < 16; g++) {
            const float4 a = red2[g][i2];
            s.x += a.x; s.y += a.y; s.z += a.z; s.w += a.w;
        }
        const float bb = b2[0];
        s.x = fmaxf(s.x + bb, 0.f); s.y = fmaxf(s.y + bb, 0.f);
        s.z = fmaxf(s.z + bb, 0.f); s.w = fmaxf(s.w + bb, 0.f);
        *(float4*)&g_ref[pt * 64 + i2 * 4] = s;
    }
}

// ---------------------------------------------------------------------------
// Kernel B (k_match v5): 512 blocks = (b, 16-patch group). 8 warps = 4 patch
// quads x 2 row halves; each warp sweeps 32 rows for 4 patches.
//   - Dual tiles: Ra[r][c]=recon(r,c), Rs[r][c]=recon(r,c+1). The (q+1,q+2)
//     packed operand is a direct LDS.64 (no pack, no cross-load dependency).
//   - 2-row argmax groups: rv = max over 4 candidates (2 rows x 2 cols),
//     track only (bv, groupBase); row+col decoded once per patch at the end
//     by bit-exact scalar recomputation, candidates checked in flat order.
// ---------------------------------------------------------------------------
__global__ void __launch_bounds__(256) k_match(float* __restrict__ out) {
    __shared__ float Ra[65][68];   // recon tile; row 64 / cols>=64 are zero
    __shared__ float Rs[65][68];   // column-shifted tile; same padding
    __shared__ float sv[16][2];    // [local patch][row half] best value
    __shared__ int   si[16][2];    // [local patch][row half] best group base
    const int t    = threadIdx.x;
    const int b    = blockIdx.x >> 6;
    const int grp  = blockIdx.x & 63;       // 64 groups of 16 patches
    const float* rb = g_recon + b * HW;

    for (int i = t; i < 65 * 68; i += 256) {
        const int row = i / 68;
        const int col = i - row * 68;
        const bool in  = (row < 64) && (col < 64);
        const bool ins = (row < 64) && (col < 63);
        Ra[row][col] = in  ? rb[row * 64 + col]     : 0.f;
        Rs[row][col] = ins ? rb[row * 64 + col + 1] : 0.f;
    }
    __syncthreads();

    const int lane = t & 31;
    const int w    = t >> 5;
    const int rh   = w & 1;                 // row half: rows [rh*32, rh*32+32)
    const int pq   = w >> 1;                // patch quad 0..3
    const float* refb = g_ref + b * HW;

    const int l0 = grp * 16 + pq * 4;       // first of 4 patches for this warp

    ull cc[4][4];
    #pragma unroll
    for (int pp = 0; pp < 4; pp++) {
        const int l  = l0 + pp;
        const int pi = l >> 5, pj = l & 31;
        const float c00 = refb[(2 * pi) * 64 + 2 * pj];
        const float c01 = refb[(2 * pi) * 64 + 2 * pj + 1];
        const float c10 = refb[(2 * pi + 1) * 64 + 2 * pj];
        const float c11 = refb[(2 * pi + 1) * 64 + 2 * pj + 1];
        cc[pp][0] = pk2(c00, c00);
        cc[pp][1] = pk2(c01, c01);
        cc[pp][2] = pk2(c10, c10);
        cc[pp][3] = pk2(c11, c11);
    }

    const int q  = lane * 2;
    const int p0 = rh * 32;

    ull a01 = *(const ull*)&Ra[p0][q];      // rows roll: a=top, b=mid, c=bot
    ull s12 = *(const ull*)&Rs[p0][q];

    float bv[4] = {-1.f, -1.f, -1.f, -1.f};
    int   bi[4] = {0, 0, 0, 0};
    int   idx   = (p0 << 6) + q;            // group-base flat idx

    #pragma unroll 4
    for (int p = p0; p < p0 + 32; p += 2) {
        const ull b01 = *(const ull*)&Ra[p + 1][q];
        const ull t12 = *(const ull*)&Rs[p + 1][q];
        const ull c01 = *(const ull*)&Ra[p + 2][q];
        const ull u12 = *(const ull*)&Rs[p + 2][q];

        #pragma unroll
        for (int pp = 0; pp < 4; pp++) {
            const ull yP = fma2(cc[pp][3], t12, fma2(cc[pp][2], b01,
                           fma2(cc[pp][1], s12, mul2(cc[pp][0], a01))));
            const ull yQ = fma2(cc[pp][3], u12, fma2(cc[pp][2], c01,
                           fma2(cc[pp][1], t12, mul2(cc[pp][0], b01))));
            float p0v, p1v; unpk2(yP, p0v, p1v);
            float q0v, q1v; unpk2(yQ, q0v, q1v);
            const float rv = fmaxf(fmaxf(p0v, p1v), fmaxf(q0v, q1v));
            if (rv > bv[pp]) { bi[pp] = idx; }
            bv[pp] = fmaxf(bv[pp], rv);
        }
        a01 = c01;
        s12 = u12;
        idx += 128;
    }

    // Warp argmax per patch; ties -> smallest group base. (Group bases order
    // identically to true flat indices for the all-zero-tie case, which
    // resolves to global index 0; positive exact cross-window ties do not
    // occur for distinct 512-term fp32 sums.)
    #pragma unroll
    for (int pp = 0; pp < 4; pp++) {
        float v = bv[pp]; int i0 = bi[pp];
        #pragma unroll
        for (int off = 16; off; off >>= 1) {
            const float v2 = __shfl_down_sync(0xffffffffu, v, off);
            const int   i2 = __shfl_down_sync(0xffffffffu, i0, off);
            if (v2 > v || (v2 == v && i2 < i0)) { v = v2; i0 = i2; }
        }
        if (lane == 0) { sv[pq * 4 + pp][rh] = v; si[pq * 4 + pp][rh] = i0; }
    }
    __syncthreads();

    // Combine halves, decode row+col (bit-exact recompute, flat order), gather.
    if (t < 16) {
        float v   = sv[t][0];
        int   bi2 = si[t][0];
        const float v1 = sv[t][1];
        const int   i1 = si[t][1];
        if (v1 > v) { v = v1; bi2 = i1; }   // half-1 bases larger -> ties keep half 0

        const int l  = grp * 16 + t;
        const int pi = l >> 5, pj = l & 31;
        const float c00 = refb[(2 * pi) * 64 + 2 * pj];
        const float c01 = refb[(2 * pi) * 64 + 2 * pj + 1];
        const float c10 = refb[(2 * pi + 1) * 64 + 2 * pj];
        const float c11 = refb[(2 * pi + 1) * 64 + 2 * pj + 1];

        const int pr = bi2 >> 6;             // winning group top row
        const int qb = bi2 & 63;             // winning column pair base
        // scalar recompute, same association order as the fma2 chain
        float y00 = c00 * Ra[pr][qb];
        y00 = fmaf(c01, Rs[pr][qb], y00);
        y00 = fmaf(c10, Ra[pr + 1][qb], y00);
        y00 = fmaf(c11, Rs[pr + 1][qb], y00);
        float y01 = c00 * Ra[pr][qb + 1];
        y01 = fmaf(c01, Rs[pr][qb + 1], y01);
        y01 = fmaf(c10, Ra[pr + 1][qb + 1], y01);
        y01 = fmaf(c11, Rs[pr + 1][qb + 1], y01);
        float y10 = c00 * Ra[pr + 1][qb];
        y10 = fmaf(c01, Rs[pr + 1][qb], y10);
        y10 = fmaf(c10, Ra[pr + 2][qb], y10);
        y10 = fmaf(c11, Rs[pr + 2][qb], y10);
        // candidates in flat order: base, base+1, base+64, base+65
        int besti;
        if      (y00 == v) besti = bi2;
        else if (y01 == v) besti = bi2 + 1;
        else if (y10 == v) besti = bi2 + 64;
        else               besti = bi2 + 65;

        const int g  = besti >> 2;           // offset // 4
        const int gi = g >> 5, gj = g & 31;
        float* o = out + b * HW + (2 * pi) * 64 + 2 * pj;
        o[0]  = Ra[2 * gi][2 * gj];
        o[1]  = Ra[2 * gi][2 * gj + 1];
        o[64] = Ra[2 * gi + 1][2 * gj];
        o[65] = Ra[2 * gi + 1][2 * gj + 1];
    }
}

extern "C" void kernel_launch(void* const* d_in, const int* in_sizes, int n_in,
                              void* d_out, int out_size) {
    const float* spade = (const float*)d_in[0];
    const float* x     = (const float*)d_in[1];
    const float* w1    = (const float*)d_in[2];
    const float* b1    = (const float*)d_in[3];
    const float* w2    = (const float*)d_in[4];
    const float* b2    = (const float*)d_in[5];
    float* out = (float*)d_out;

    k_fused<<<512, 256>>>(spade, x, w1, w2, b1, b2);
    k_match<<<512, 256>>>(out);
}

// round 13
// speedup vs baseline: 1.8304x; 1.0065x over previous
#include <cuda_runtime.h>

#define CH     512
#define HW     4096        // 64*64
#define NPIX   32768       // 8 * 4096

// Static device scratch (no dynamic allocation allowed).
__device__ float g_recon[NPIX];
__device__ float g_ref[NPIX];

// ---- packed f32x2 helpers (Blackwell FFMA2 path, PTX-only) -----------------
typedef unsigned long long ull;
__device__ __forceinline__ ull pk2(float lo, float hi) {
    ull r; asm("mov.b64 %0, {%1, %2};" : "=l"(r) : "f"(lo), "f"(hi)); return r;
}
__device__ __forceinline__ void unpk2(ull v, float& lo, float& hi) {
    asm("mov.b64 {%0, %1}, %2;" : "=f"(lo), "=f"(hi) : "l"(v));
}
__device__ __forceinline__ ull fma2(ull a, ull b, ull c) {
    ull d; asm("fma.rn.f32x2 %0, %1, %2, %3;" : "=l"(d) : "l"(a), "l"(b), "l"(c));
    return d;
}
__device__ __forceinline__ ull mul2(ull a, ull b) {
    ull d; asm("mul.rn.f32x2 %0, %1, %2;" : "=l"(d) : "l"(a), "l"(b)); return d;
}

// ---------------------------------------------------------------------------
// Kernel A (fused dot + reduce) — unchanged from R6 (near DRAM roof).
// ---------------------------------------------------------------------------
__global__ void __launch_bounds__(256) k_fused(
        const float* __restrict__ spade, const float* __restrict__ x,
        const float* __restrict__ w1, const float* __restrict__ w2,
        const float* __restrict__ b1, const float* __restrict__ b2) {
    __shared__ float2 ws[CH];                 // (w1, w2) pairs
    __shared__ float4 red1[16][16];           // [group][float4 slot]
    __shared__ float4 red2[16][16];
    const int t = threadIdx.x;
    for (int c = t; c < CH; c += 256) ws[c] = make_float2(w1[c], w2[c]);
    __syncthreads();

    const int pt  = blockIdx.x;               // 64-px tile index (0..511)
    const int b   = pt >> 6;                  // batch
    const int hw0 = (pt & 63) * 64;           // tile base within the image
    const int i   = t & 15;                   // float4 slot (4 px)
    const int j   = t >> 4;                   // channel group (32 ch)

    const size_t base = (size_t)b * CH * HW + (size_t)(j * 32) * HW + hw0 + i * 4;
    const float4* fp = (const float4*)(spade + base);
    const float4* xp = (const float4*)(x + base);
    const float2* wp = ws + j * 32;

    float4 a1 = make_float4(0.f, 0.f, 0.f, 0.f);
    float4 a2 = make_float4(0.f, 0.f, 0.f, 0.f);
    #pragma unroll 8
    for (int c = 0; c < 32; c++) {
        float4 f = __ldcs(fp + (size_t)c * (HW / 4));
        float4 v = __ldcs(xp + (size_t)c * (HW / 4));
        const float2 w = wp[c];
        a1.x += f.x * w.x; a1.y += f.y * w.x; a1.z += f.z * w.x; a1.w += f.w * w.x;
        a2.x += v.x * w.y; a2.y += v.y * w.y; a2.z += v.z * w.y; a2.w += v.w * w.y;
    }
    red1[j][i] = a1;
    red2[j][i] = a2;
    __syncthreads();

    if (t < 16) {
        float4 s = make_float4(0.f, 0.f, 0.f, 0.f);
        #pragma unroll
        for (int g = 0; g < 16; g++) {
            const float4 a = red1[g][t];
            s.x += a.x; s.y += a.y; s.z += a.z; s.w += a.w;
        }
        const float bb = b1[0];
        s.x = fmaxf(s.x + bb, 0.f); s.y = fmaxf(s.y + bb, 0.f);
        s.z = fmaxf(s.z + bb, 0.f); s.w = fmaxf(s.w + bb, 0.f);
        *(float4*)&g_recon[pt * 64 + t * 4] = s;
    } else if (t >= 32 && t < 48) {
        const int i2 = t - 32;
        float4 s = make_float4(0.f, 0.f, 0.f, 0.f);
        #pragma unroll
        for (int g = 0; g < 16; g++) {
            const float4 a = red2[g][i2];
            s.x += a.x; s.y += a.y; s.z += a.z; s.w += a.w;
        }
        const float bb = b2[0];
        s.x = fmaxf(s.x + bb, 0.f); s.y = fmaxf(s.y + bb, 0.f);
        s.z = fmaxf(s.z + bb, 0.f); s.w = fmaxf(s.w + bb, 0.f);
        *(float4*)&g_ref[pt * 64 + i2 * 4] = s;
    }
}

// ---------------------------------------------------------------------------
// Kernel B (k_match v8 = R11 + carveout + group-of-4 decode):
// 512 blocks = (b, 16-patch group). 8 warps = 4 patch quads x 2 row halves;
// each warp sweeps 32 rows for 4 patches. Dual tiles Ra/Rs; 2-row argmax
// groups tracking (bv, groupBase) only. KEY: output needs argmax//4 =
// p*16 + q//4, and the packed pair (q,q+1) always shares the same //4 group,
// so only the winning ROW needs decoding (one pair recompute at the end).
// ---------------------------------------------------------------------------
__global__ void __launch_bounds__(256) k_match(float* __restrict__ out) {
    __shared__ float Ra[65][68];   // recon tile; row 64 / cols>=64 are zero
    __shared__ float Rs[65][68];   // column-shifted tile; same padding
    __shared__ float sv[16][2];    // [local patch][row half] best value
    __shared__ int   si[16][2];    // [local patch][row half] best group base
    const int t    = threadIdx.x;
    const int b    = blockIdx.x >> 6;
    const int grp  = blockIdx.x & 63;       // 64 groups of 16 patches
    const float* rb = g_recon + b * HW;

    for (int i = t; i < 65 * 68; i += 256) {
        const int row = i / 68;
        const int col = i - row * 68;
        const bool in  = (row < 64) && (col < 64);
        const bool ins = (row < 64) && (col < 63);
        Ra[row][col] = in  ? rb[row * 64 + col]     : 0.f;
        Rs[row][col] = ins ? rb[row * 64 + col + 1] : 0.f;
    }
    __syncthreads();

    const int lane = t & 31;
    const int w    = t >> 5;
    const int rh   = w & 1;                 // row half: rows [rh*32, rh*32+32)
    const int pq   = w >> 1;                // patch quad 0..3
    const float* refb = g_ref + b * HW;

    const int l0 = grp * 16 + pq * 4;       // first of 4 patches for this warp

    ull cc[4][4];
    #pragma unroll
    for (int pp = 0; pp < 4; pp++) {
        const int l  = l0 + pp;
        const int pi = l >> 5, pj = l & 31;
        const float c00 = refb[(2 * pi) * 64 + 2 * pj];
        const float c01 = refb[(2 * pi) * 64 + 2 * pj + 1];
        const float c10 = refb[(2 * pi + 1) * 64 + 2 * pj];
        const float c11 = refb[(2 * pi + 1) * 64 + 2 * pj + 1];
        cc[pp][0] = pk2(c00, c00);
        cc[pp][1] = pk2(c01, c01);
        cc[pp][2] = pk2(c10, c10);
        cc[pp][3] = pk2(c11, c11);
    }

    const int q  = lane * 2;
    const int p0 = rh * 32;

    ull a01 = *(const ull*)&Ra[p0][q];      // rows roll: a=top, b=mid, c=bot
    ull s12 = *(const ull*)&Rs[p0][q];

    float bv[4] = {-1.f, -1.f, -1.f, -1.f};
    int   bi[4] = {0, 0, 0, 0};
    int   idx   = (p0 << 6) + q;            // group-base flat idx

    #pragma unroll 4
    for (int p = p0; p < p0 + 32; p += 2) {
        const ull b01 = *(const ull*)&Ra[p + 1][q];
        const ull t12 = *(const ull*)&Rs[p + 1][q];
        const ull c01 = *(const ull*)&Ra[p + 2][q];
        const ull u12 = *(const ull*)&Rs[p + 2][q];

        #pragma unroll
        for (int pp = 0; pp < 4; pp++) {
            const ull yP = fma2(cc[pp][3], t12, fma2(cc[pp][2], b01,
                           fma2(cc[pp][1], s12, mul2(cc[pp][0], a01))));
            const ull yQ = fma2(cc[pp][3], u12, fma2(cc[pp][2], c01,
                           fma2(cc[pp][1], t12, mul2(cc[pp][0], b01))));
            float p0v, p1v; unpk2(yP, p0v, p1v);
            float q0v, q1v; unpk2(yQ, q0v, q1v);
            const float rv = fmaxf(fmaxf(p0v, p1v), fmaxf(q0v, q1v));
            if (rv > bv[pp]) { bi[pp] = idx; }
            bv[pp] = fmaxf(bv[pp], rv);
        }
        a01 = c01;
        s12 = u12;
        idx += 128;
    }

    // Warp argmax per patch; ties -> smallest group base (row-major order).
    #pragma unroll
    for (int pp = 0; pp < 4; pp++) {
        float v = bv[pp]; int i0 = bi[pp];
        #pragma unroll
        for (int off = 16; off; off >>= 1) {
            const float v2 = __shfl_down_sync(0xffffffffu, v, off);
            const int   i2 = __shfl_down_sync(0xffffffffu, i0, off);
            if (v2 > v || (v2 == v && i2 < i0)) { v = v2; i0 = i2; }
        }
        if (lane == 0) { sv[pq * 4 + pp][rh] = v; si[pq * 4 + pp][rh] = i0; }
    }
    __syncthreads();

    // Combine halves; decode ONLY the winning row (column pair shares the
    // //4 group, so it cannot affect the gathered patch). Earlier row wins
    // on tie (first occurrence).
    if (t < 16) {
        float v   = sv[t][0];
        int   bw  = si[t][0];
        const float v1 = sv[t][1];
        const int   i1 = si[t][1];
        if (v1 > v) { v = v1; bw = i1; }    // half-1 bases larger -> ties keep half 0

        const int l  = grp * 16 + t;
        const int pi = l >> 5, pj = l & 31;
        const float c00 = refb[(2 * pi) * 64 + 2 * pj];
        const float c01 = refb[(2 * pi) * 64 + 2 * pj + 1];
        const float c10 = refb[(2 * pi + 1) * 64 + 2 * pj];
        const float c11 = refb[(2 * pi + 1) * 64 + 2 * pj + 1];

        const int pr = bw >> 6;              // group top row
        const int qb = bw & 63;              // column pair base
        // bit-exact recompute of the top row's pair (same association order)
        float y0 = c00 * Ra[pr][qb];
        y0 = fmaf(c01, Rs[pr][qb], y0);
        y0 = fmaf(c10, Ra[pr + 1][qb], y0);
        y0 = fmaf(c11, Rs[pr + 1][qb], y0);
        float y1 = c00 * Ra[pr][qb + 1];
        y1 = fmaf(c01, Rs[pr][qb + 1], y1);
        y1 = fmaf(c10, Ra[pr + 1][qb + 1], y1);
        y1 = fmaf(c11, Rs[pr + 1][qb + 1], y1);
        const int besti = (fmaxf(y0, y1) == v) ? bw : bw + 64;

        const int g  = besti >> 2;           // offset // 4
        const int gi = g >> 5, gj = g & 31;
        float* o = out + b * HW + (2 * pi) * 64 + 2 * pj;
        o[0]  = Ra[2 * gi][2 * gj];
        o[1]  = Ra[2 * gi][2 * gj + 1];
        o[64] = Ra[2 * gi + 1][2 * gj];
        o[65] = Ra[2 * gi + 1][2 * gj + 1];
    }
}

extern "C" void kernel_launch(void* const* d_in, const int* in_sizes, int n_in,
                              void* d_out, int out_size) {
    const float* spade = (const float*)d_in[0];
    const float* x     = (const float*)d_in[1];
    const float* w1    = (const float*)d_in[2];
    const float* b1    = (const float*)d_in[3];
    const float* w2    = (const float*)d_in[4];
    const float* b2    = (const float*)d_in[5];
    float* out = (float*)d_out;

    // Raise the L1/SMEM carveout so 4 k_match blocks (4 x 35.6 KB) fit per SM.
    // Host-side, immediate, idempotent, capture-safe (not a stream op).
    cudaFuncSetAttribute(k_match, cudaFuncAttributePreferredSharedMemoryCarveout, 100);

    k_fused<<<512, 256>>>(spade, x, w1, w2, b1, b2);
    k_match<<<512, 256>>>(out);
}

// round 14
// speedup vs baseline: 1.9323x; 1.0557x over previous
#include <cuda_runtime.h>

#define CH     512
#define HW     4096        // 64*64
#define NPIX   32768       // 8 * 4096

// Static device scratch (no dynamic allocation allowed).
__device__ float g_recon[NPIX];
__device__ float g_ref[NPIX];

// ---- packed f32x2 helpers (Blackwell FFMA2 path, PTX-only) -----------------
typedef unsigned long long ull;
__device__ __forceinline__ ull pk2(float lo, float hi) {
    ull r; asm("mov.b64 %0, {%1, %2};" : "=l"(r) : "f"(lo), "f"(hi)); return r;
}
__device__ __forceinline__ void unpk2(ull v, float& lo, float& hi) {
    asm("mov.b64 {%0, %1}, %2;" : "=f"(lo), "=f"(hi) : "l"(v));
}
__device__ __forceinline__ ull fma2(ull a, ull b, ull c) {
    ull d; asm("fma.rn.f32x2 %0, %1, %2, %3;" : "=l"(d) : "l"(a), "l"(b), "l"(c));
    return d;
}
__device__ __forceinline__ ull mul2(ull a, ull b) {
    ull d; asm("mul.rn.f32x2 %0, %1, %2;" : "=l"(d) : "l"(a), "l"(b)); return d;
}

// ---------------------------------------------------------------------------
// Kernel A (fused dot + reduce) — unchanged from R6 (near DRAM roof).
// ---------------------------------------------------------------------------
__global__ void __launch_bounds__(256) k_fused(
        const float* __restrict__ spade, const float* __restrict__ x,
        const float* __restrict__ w1, const float* __restrict__ w2,
        const float* __restrict__ b1, const float* __restrict__ b2) {
    __shared__ float2 ws[CH];                 // (w1, w2) pairs
    __shared__ float4 red1[16][16];           // [group][float4 slot]
    __shared__ float4 red2[16][16];
    const int t = threadIdx.x;
    for (int c = t; c < CH; c += 256) ws[c] = make_float2(w1[c], w2[c]);
    __syncthreads();

    const int pt  = blockIdx.x;               // 64-px tile index (0..511)
    const int b   = pt >> 6;                  // batch
    const int hw0 = (pt & 63) * 64;           // tile base within the image
    const int i   = t & 15;                   // float4 slot (4 px)
    const int j   = t >> 4;                   // channel group (32 ch)

    const size_t base = (size_t)b * CH * HW + (size_t)(j * 32) * HW + hw0 + i * 4;
    const float4* fp = (const float4*)(spade + base);
    const float4* xp = (const float4*)(x + base);
    const float2* wp = ws + j * 32;

    float4 a1 = make_float4(0.f, 0.f, 0.f, 0.f);
    float4 a2 = make_float4(0.f, 0.f, 0.f, 0.f);
    #pragma unroll 8
    for (int c = 0; c < 32; c++) {
        float4 f = __ldcs(fp + (size_t)c * (HW / 4));
        float4 v = __ldcs(xp + (size_t)c * (HW / 4));
        const float2 w = wp[c];
        a1.x += f.x * w.x; a1.y += f.y * w.x; a1.z += f.z * w.x; a1.w += f.w * w.x;
        a2.x += v.x * w.y; a2.y += v.y * w.y; a2.z += v.z * w.y; a2.w += v.w * w.y;
    }
    red1[j][i] = a1;
    red2[j][i] = a2;
    __syncthreads();

    if (t < 16) {
        float4 s = make_float4(0.f, 0.f, 0.f, 0.f);
        #pragma unroll
        for (int g = 0; g < 16; g++) {
            const float4 a = red1[g][t];
            s.x += a.x; s.y += a.y; s.z += a.z; s.w += a.w;
        }
        const float bb = b1[0];
        s.x = fmaxf(s.x + bb, 0.f); s.y = fmaxf(s.y + bb, 0.f);
        s.z = fmaxf(s.z + bb, 0.f); s.w = fmaxf(s.w + bb, 0.f);
        *(float4*)&g_recon[pt * 64 + t * 4] = s;
    } else if (t >= 32 && t < 48) {
        const int i2 = t - 32;
        float4 s = make_float4(0.f, 0.f, 0.f, 0.f);
        #pragma unroll
        for (int g = 0; g < 16; g++) {
            const float4 a = red2[g][i2];
            s.x += a.x; s.y += a.y; s.z += a.z; s.w += a.w;
        }
        const float bb = b2[0];
        s.x = fmaxf(s.x + bb, 0.f); s.y = fmaxf(s.y + bb, 0.f);
        s.z = fmaxf(s.z + bb, 0.f); s.w = fmaxf(s.w + bb, 0.f);
        *(float4*)&g_ref[pt * 64 + i2 * 4] = s;
    }
}

// ---------------------------------------------------------------------------
// Kernel B (k_match v9 = R13 sweep + vectorized fill):
// Fill: thread (r = t>>2, qx = t&3) loads its 16-col quarter with 4 LDG.128,
// stores 4 STS.128 to Ra and 4 register-shifted STS.128 to Rs. Padding
// zeroed by two small vector loops. ~30 instr/thread vs ~500 before.
// Sweep/argmax/decode identical to R13 (group-of-4 row-only decode).
// ---------------------------------------------------------------------------
__global__ void __launch_bounds__(256) k_match(float* __restrict__ out) {
    __shared__ float Ra[65][68];   // recon tile; row 64 / cols>=64 are zero
    __shared__ float Rs[65][68];   // column-shifted tile; same padding
    __shared__ float sv[16][2];    // [local patch][row half] best value
    __shared__ int   si[16][2];    // [local patch][row half] best group base
    const int t    = threadIdx.x;
    const int b    = blockIdx.x >> 6;
    const int grp  = blockIdx.x & 63;       // 64 groups of 16 patches
    const float* rb = g_recon + b * HW;

    // ---- vectorized fill ----
    {
        const int r  = t >> 2;              // row 0..63
        const int qx = t & 3;               // 16-col quarter
        const float4* src = (const float4*)(rb + r * 64) + qx * 4;
        const float4 f0 = src[0];
        const float4 f1 = src[1];
        const float4 f2 = src[2];
        const float4 f3 = src[3];
        // 17th element: col 16*qx+16 (valid for qx<3; col 64 -> zero pad)
        const float e16 = (qx == 3) ? 0.f : ((const float*)src)[16];
        const int c0 = qx * 16;
        *(float4*)&Ra[r][c0]      = f0;
        *(float4*)&Ra[r][c0 + 4]  = f1;
        *(float4*)&Ra[r][c0 + 8]  = f2;
        *(float4*)&Ra[r][c0 + 12] = f3;
        *(float4*)&Rs[r][c0]      = make_float4(f0.y, f0.z, f0.w, f1.x);
        *(float4*)&Rs[r][c0 + 4]  = make_float4(f1.y, f1.z, f1.w, f2.x);
        *(float4*)&Rs[r][c0 + 8]  = make_float4(f2.y, f2.z, f2.w, f3.x);
        *(float4*)&Rs[r][c0 + 12] = make_float4(f3.y, f3.z, f3.w, e16);
        // padding: cols 64..67 for rows 0..63
        if (t < 64) {
            *(float4*)&Ra[t][64] = make_float4(0.f, 0.f, 0.f, 0.f);
            *(float4*)&Rs[t][64] = make_float4(0.f, 0.f, 0.f, 0.f);
        }
        // padding: row 64 (all 68 cols)
        if (t >= 64 && t < 81) {
            const int c = (t - 64) * 4;
            *(float4*)&Ra[64][c] = make_float4(0.f, 0.f, 0.f, 0.f);
            *(float4*)&Rs[64][c] = make_float4(0.f, 0.f, 0.f, 0.f);
        }
    }
    __syncthreads();

    const int lane = t & 31;
    const int w    = t >> 5;
    const int rh   = w & 1;                 // row half: rows [rh*32, rh*32+32)
    const int pq   = w >> 1;                // patch quad 0..3
    const float* refb = g_ref + b * HW;

    const int l0 = grp * 16 + pq * 4;       // first of 4 patches for this warp

    ull cc[4][4];
    #pragma unroll
    for (int pp = 0; pp < 4; pp++) {
        const int l  = l0 + pp;
        const int pi = l >> 5, pj = l & 31;
        const float c00 = refb[(2 * pi) * 64 + 2 * pj];
        const float c01 = refb[(2 * pi) * 64 + 2 * pj + 1];
        const float c10 = refb[(2 * pi + 1) * 64 + 2 * pj];
        const float c11 = refb[(2 * pi + 1) * 64 + 2 * pj + 1];
        cc[pp][0] = pk2(c00, c00);
        cc[pp][1] = pk2(c01, c01);
        cc[pp][2] = pk2(c10, c10);
        cc[pp][3] = pk2(c11, c11);
    }

    const int q  = lane * 2;
    const int p0 = rh * 32;

    ull a01 = *(const ull*)&Ra[p0][q];      // rows roll: a=top, b=mid, c=bot
    ull s12 = *(const ull*)&Rs[p0][q];

    float bv[4] = {-1.f, -1.f, -1.f, -1.f};
    int   bi[4] = {0, 0, 0, 0};
    int   idx   = (p0 << 6) + q;            // group-base flat idx

    #pragma unroll 4
    for (int p = p0; p < p0 + 32; p += 2) {
        const ull b01 = *(const ull*)&Ra[p + 1][q];
        const ull t12 = *(const ull*)&Rs[p + 1][q];
        const ull c01 = *(const ull*)&Ra[p + 2][q];
        const ull u12 = *(const ull*)&Rs[p + 2][q];

        #pragma unroll
        for (int pp = 0; pp < 4; pp++) {
            const ull yP = fma2(cc[pp][3], t12, fma2(cc[pp][2], b01,
                           fma2(cc[pp][1], s12, mul2(cc[pp][0], a01))));
            const ull yQ = fma2(cc[pp][3], u12, fma2(cc[pp][2], c01,
                           fma2(cc[pp][1], t12, mul2(cc[pp][0], b01))));
            float p0v, p1v; unpk2(yP, p0v, p1v);
            float q0v, q1v; unpk2(yQ, q0v, q1v);
            const float rv = fmaxf(fmaxf(p0v, p1v), fmaxf(q0v, q1v));
            if (rv > bv[pp]) { bi[pp] = idx; }
            bv[pp] = fmaxf(bv[pp], rv);
        }
        a01 = c01;
        s12 = u12;
        idx += 128;
    }

    // Warp argmax per patch; ties -> smallest group base (row-major order).
    #pragma unroll
    for (int pp = 0; pp < 4; pp++) {
        float v = bv[pp]; int i0 = bi[pp];
        #pragma unroll
        for (int off = 16; off; off >>= 1) {
            const float v2 = __shfl_down_sync(0xffffffffu, v, off);
            const int   i2 = __shfl_down_sync(0xffffffffu, i0, off);
            if (v2 > v || (v2 == v && i2 < i0)) { v = v2; i0 = i2; }
        }
        if (lane == 0) { sv[pq * 4 + pp][rh] = v; si[pq * 4 + pp][rh] = i0; }
    }
    __syncthreads();

    // Combine halves; decode ONLY the winning row (column pair shares the
    // //4 group, so it cannot affect the gathered patch). Earlier row wins
    // on tie (first occurrence).
    if (t < 16) {
        float v   = sv[t][0];
        int   bw  = si[t][0];
        const float v1 = sv[t][1];
        const int   i1 = si[t][1];
        if (v1 > v) { v = v1; bw = i1; }    // half-1 bases larger -> ties keep half 0

        const int l  = grp * 16 + t;
        const int pi = l >> 5, pj = l & 31;
        const float c00 = refb[(2 * pi) * 64 + 2 * pj];
        const float c01 = refb[(2 * pi) * 64 + 2 * pj + 1];
        const float c10 = refb[(2 * pi + 1) * 64 + 2 * pj];
        const float c11 = refb[(2 * pi + 1) * 64 + 2 * pj + 1];

        const int pr = bw >> 6;              // group top row
        const int qb = bw & 63;              // column pair base
        // bit-exact recompute of the top row's pair (same association order)
        float y0 = c00 * Ra[pr][qb];
        y0 = fmaf(c01, Rs[pr][qb], y0);
        y0 = fmaf(c10, Ra[pr + 1][qb], y0);
        y0 = fmaf(c11, Rs[pr + 1][qb], y0);
        float y1 = c00 * Ra[pr][qb + 1];
        y1 = fmaf(c01, Rs[pr][qb + 1], y1);
        y1 = fmaf(c10, Ra[pr + 1][qb + 1], y1);
        y1 = fmaf(c11, Rs[pr + 1][qb + 1], y1);
        const int besti = (fmaxf(y0, y1) == v) ? bw : bw + 64;

        const int g  = besti >> 2;           // offset // 4
        const int gi = g >> 5, gj = g & 31;
        float* o = out + b * HW + (2 * pi) * 64 + 2 * pj;
        o[0]  = Ra[2 * gi][2 * gj];
        o[1]  = Ra[2 * gi][2 * gj + 1];
        o[64] = Ra[2 * gi + 1][2 * gj];
        o[65] = Ra[2 * gi + 1][2 * gj + 1];
    }
}

extern "C" void kernel_launch(void* const* d_in, const int* in_sizes, int n_in,
                              void* d_out, int out_size) {
    const float* spade = (const float*)d_in[0];
    const float* x     = (const float*)d_in[1];
    const float* w1    = (const float*)d_in[2];
    const float* b1    = (const float*)d_in[3];
    const float* w2    = (const float*)d_in[4];
    const float* b2    = (const float*)d_in[5];
    float* out = (float*)d_out;

    k_fused<<<512, 256>>>(spade, x, w1, w2, b1, b2);
    k_match<<<512, 256>>>(out);
}